// round 10
// baseline (speedup 1.0000x reference)
#include <cuda_runtime.h>

#define B_ROWS   8192
#define NBINS    125
#define M_CAND   4096
#define NTOT     (NBINS * M_CAND)
#define NTHREADS 256
#define NWARPS   8
#define EARTH_R  3958.8f
#define DEG2RAD  0.017453292519943295f
#define LOG2E    1.4426950408889634f
// K0 = -4 * R * log2(e): chord-space logit slope (log2 units), slope at c=0
#define K0_CONST (-4.0f * EARTH_R * LOG2E)

// Static scratch (no allocations allowed)
__device__ float4 g_xyz[NTOT];     // candidate unit vectors (x,y,z,0)
__device__ float4 g_rowv[B_ROWS];  // row unit vectors (x,y,z,0)
__device__ int2   g_meta[B_ROWS];  // (base index, count) per row
__device__ float  g_soft [B_ROWS];
__device__ float  g_valid[B_ROWS];
__device__ int    g_ticket;

// ---------------------------------------------------------------------------
// Kernel 1 (merged prep): candidates -> unit vectors; rows -> unit vector +
// (base, count) meta; ticket reset.
// ---------------------------------------------------------------------------
__global__ __launch_bounds__(256)
void prep_kernel(const float2* __restrict__ bin_coords,
                 const float* __restrict__ preds,
                 const long long* __restrict__ x_vals,
                 const long long* __restrict__ bin_counts) {
    int i = blockIdx.x * 256 + threadIdx.x;
    if (i == 0) g_ticket = 0;
    if (i < NTOT) {
        float2 c = bin_coords[i];             // (lon, lat) degrees
        float lon = c.x * DEG2RAD;
        float lat = c.y * DEG2RAD;
        float slat, clat, slon, clon;
        __sincosf(lat, &slat, &clat);
        __sincosf(lon, &slon, &clon);
        g_xyz[i] = make_float4(clat * clon, clat * slon, slat, 0.0f);
    } else if (i < NTOT + B_ROWS) {
        int b = i - NTOT;
        long long bin_id = x_vals[b * 3 + 0] * 25 + x_vals[b * 3 + 1] * 5 + x_vals[b * 3 + 2];
        if (bin_id < 0) bin_id = 0;
        if (bin_id >= NBINS) bin_id = NBINS - 1;
        int count = (int)bin_counts[bin_id];
        if (count < 0) count = 0;
        if (count > M_CAND) count = M_CAND;
        float lon = preds[b * 2 + 0] * DEG2RAD;
        float lat = preds[b * 2 + 1] * DEG2RAD;
        float slat, clat, slon, clon;
        sincosf(lat, &slat, &clat);           // libm accuracy once per row
        sincosf(lon, &slon, &clon);
        g_rowv[b] = make_float4(clat * clon, clat * slon, slat, 0.0f);
        g_meta[b] = make_int2((int)bin_id * M_CAND, count);
    }
}

// ---------------------------------------------------------------------------
// Kernel 2: SINGLE pass — online logsumexp in chord space with fixed slope.
// No smem candidate cache, no mid-kernel barriers. Fused final reduction.
// ---------------------------------------------------------------------------
__global__ __launch_bounds__(NTHREADS)
void softbin_main_kernel(float* __restrict__ out) {
    __shared__ float sh_m[NWARPS];
    __shared__ float sh_s[NWARPS];

    const int b    = blockIdx.x;
    const int tid  = threadIdx.x;
    const int warp = tid >> 5;
    const int lane = tid & 31;

    const int2  mt  = g_meta[b];
    const int base  = mt.x;
    const int count = mt.y;
    const float4 rv = g_rowv[b];              // broadcast LDG.128
    const float px = rv.x, py = rv.y, pz = rv.z;

    const float4* __restrict__ cand = g_xyz + base;

    // Online state: m = smallest chord seen, s = sum of exp2(K0*(c - m)).
    float m = 1.0e30f;
    float s = 0.0f;

    #pragma unroll 4
    for (int j = tid; j < count; j += NTHREADS) {
        float4 c = __ldg(&cand[j]);
        float dx = px - c.x;
        float dy = py - c.y;
        float dz = pz - c.z;
        float s2 = fmaf(dx, dx, fmaf(dy, dy, dz * dz));
        float cc = __fsqrt_rn(s2);
        // e = exp2(K0 * |cc - m|)   (K0 < 0, so exponent <= 0; underflows to 0
        // for anything far outside the soft-min window — natural windowing)
        float e  = exp2f(K0_CONST * fabsf(cc - m));
        bool newmin = cc < m;
        s = newmin ? fmaf(s, e, 1.0f) : (s + e);
        m = fminf(m, cc);
    }

    // Warp-level (m, s) combine
    #pragma unroll
    for (int off = 16; off > 0; off >>= 1) {
        float mo = __shfl_xor_sync(0xffffffffu, m, off);
        float so = __shfl_xor_sync(0xffffffffu, s, off);
        float mn = fminf(m, mo);
        s = s  * exp2f(K0_CONST * (m  - mn))
          + so * exp2f(K0_CONST * (mo - mn));
        m = mn;
    }
    if (lane == 0) { sh_m[warp] = m; sh_s[warp] = s; }
    __syncthreads();

    if (tid == 0) {
        float M0 = sh_m[0], S0 = sh_s[0];
        #pragma unroll
        for (int w = 1; w < NWARPS; ++w) {
            float mo = sh_m[w], so = sh_s[w];
            float mn = fminf(M0, mo);
            S0 = S0 * exp2f(K0_CONST * (M0 - mn))
               + so * exp2f(K0_CONST * (mo - mn));
            M0 = mn;
        }
        float soft = 0.0f;
        if (count > 0) {
            // exact d_min from chord; S0 approximates sum of exp(-4(d_i - d_min))
            float d_min = (2.0f * EARTH_R) * asinf(fminf(0.5f * M0, 1.0f));
            soft = d_min - 0.25f * logf(S0);
        }
        g_soft[b]  = soft;
        g_valid[b] = (count > 0) ? 1.0f : 0.0f;
    }

    // ---- fused final reduction: last block to arrive finishes ----
    __shared__ int sh_last;
    __threadfence();
    __syncthreads();
    if (tid == 0) {
        int t = atomicAdd(&g_ticket, 1);
        sh_last = (t == gridDim.x - 1) ? 1 : 0;
    }
    __syncthreads();
    if (sh_last) {
        __shared__ float rs[NTHREADS];
        __shared__ float rvv[NTHREADS];
        float ss = 0.0f, vv = 0.0f;
        for (int i = tid; i < B_ROWS; i += NTHREADS) {
            ss += g_soft[i];
            vv += g_valid[i];
        }
        rs[tid] = ss;
        rvv[tid] = vv;
        __syncthreads();
        #pragma unroll
        for (int off = NTHREADS / 2; off > 0; off >>= 1) {
            if (tid < off) {
                rs[tid]  += rs[tid + off];
                rvv[tid] += rvv[tid + off];
            }
            __syncthreads();
        }
        if (tid == 0) out[0] = rs[0] / fmaxf(rvv[0], 1.0f);
    }
}

extern "C" void kernel_launch(void* const* d_in, const int* in_sizes, int n_in,
                              void* d_out, int out_size) {
    // Identify inputs by element count (all four are distinct).
    const float*     preds      = 0;   // 16384
    const float2*    bin_coords = 0;   // 1024000
    const long long* x_vals     = 0;   // 24576
    const long long* bin_counts = 0;   // 125
    for (int i = 0; i < n_in; ++i) {
        switch (in_sizes[i]) {
            case 16384:   preds      = (const float*)d_in[i];     break;
            case 1024000: bin_coords = (const float2*)d_in[i];    break;
            case 24576:   x_vals     = (const long long*)d_in[i]; break;
            case 125:     bin_counts = (const long long*)d_in[i]; break;
        }
    }
    float* out = (float*)d_out;

    const int prep_total = NTOT + B_ROWS;
    prep_kernel<<<(prep_total + 255) / 256, 256>>>(bin_coords, preds, x_vals, bin_counts);
    softbin_main_kernel<<<B_ROWS, NTHREADS>>>(out);
}

// round 13
// speedup vs baseline: 1.3667x; 1.3667x over previous
#include <cuda_runtime.h>

#define B_ROWS   8192
#define NBINS    125
#define M_CAND   4096
#define NTOT     (NBINS * M_CAND)
#define NTHREADS 128
#define NWARPS   4
#define EARTH_R  3958.8f
#define DEG2RAD  0.017453292519943295f
#define LOG2E    1.4426950408889634f
#define K0_CONST (-4.0f * EARTH_R * LOG2E)   /* chord-space logit slope, log2 */

// Static scratch (no allocations allowed)
__device__ float4 g_xyz[NTOT];     // candidate unit vectors (x,y,z,0)
__device__ float4 g_rowv[B_ROWS];  // row unit vectors
__device__ int2   g_meta[B_ROWS];  // (base index, count) per row
__device__ float2 g_sv[B_ROWS];    // (soft, valid) per row

// ---------------------------------------------------------------------------
// Kernel 1 (merged prep): candidates -> unit vectors; rows -> unit vector +
// (base, count) meta.
// ---------------------------------------------------------------------------
__global__ __launch_bounds__(256)
void prep_kernel(const float2* __restrict__ bin_coords,
                 const float* __restrict__ preds,
                 const long long* __restrict__ x_vals,
                 const long long* __restrict__ bin_counts) {
    int i = blockIdx.x * 256 + threadIdx.x;
    if (i < NTOT) {
        float2 c = bin_coords[i];             // (lon, lat) degrees
        float lon = c.x * DEG2RAD;
        float lat = c.y * DEG2RAD;
        float slat, clat, slon, clon;
        __sincosf(lat, &slat, &clat);
        __sincosf(lon, &slon, &clon);
        g_xyz[i] = make_float4(clat * clon, clat * slon, slat, 0.0f);
    } else if (i < NTOT + B_ROWS) {
        int b = i - NTOT;
        long long bin_id = x_vals[b * 3 + 0] * 25 + x_vals[b * 3 + 1] * 5 + x_vals[b * 3 + 2];
        if (bin_id < 0) bin_id = 0;
        if (bin_id >= NBINS) bin_id = NBINS - 1;
        int count = (int)bin_counts[bin_id];
        if (count < 0) count = 0;
        if (count > M_CAND) count = M_CAND;
        float lon = preds[b * 2 + 0] * DEG2RAD;
        float lat = preds[b * 2 + 1] * DEG2RAD;
        float slat, clat, slon, clon;
        sincosf(lat, &slat, &clat);           // libm accuracy once per row
        sincosf(lon, &slon, &clon);
        g_rowv[b] = make_float4(clat * clon, clat * slon, slat, 0.0f);
        g_meta[b] = make_int2((int)bin_id * M_CAND, count);
    }
}

// ---------------------------------------------------------------------------
// Kernel 2: row-centric single pass, online chord-space logsumexp with TWO
// independent accumulators per thread (halves the loop-carried chain).
// ---------------------------------------------------------------------------
__global__ __launch_bounds__(NTHREADS)
void softbin_main_kernel() {
    __shared__ float sh_m[NWARPS];
    __shared__ float sh_s[NWARPS];

    const int b    = blockIdx.x;
    const int tid  = threadIdx.x;
    const int warp = tid >> 5;
    const int lane = tid & 31;

    const int2  mt  = g_meta[b];
    const int base  = mt.x;
    const int count = mt.y;
    const float4 rv = g_rowv[b];              // broadcast LDG.128
    const float px = rv.x, py = rv.y, pz = rv.z;

    const float4* __restrict__ cand = g_xyz + base;

    // Two independent online states (even/odd streams)
    float m0 = 1.0e30f, s0 = 0.0f;
    float m1 = 1.0e30f, s1 = 0.0f;

    int j = tid;
    for (; j + NTHREADS < count; j += 2 * NTHREADS) {
        float4 c0 = __ldg(&cand[j]);
        float4 c1 = __ldg(&cand[j + NTHREADS]);
        {
            float dx = px - c0.x, dy = py - c0.y, dz = pz - c0.z;
            float s2 = fmaf(dx, dx, fmaf(dy, dy, dz * dz));
            float cc = __fsqrt_rn(s2);
            float e  = exp2f(K0_CONST * fabsf(cc - m0));
            s0 = (cc < m0) ? fmaf(s0, e, 1.0f) : (s0 + e);
            m0 = fminf(m0, cc);
        }
        {
            float dx = px - c1.x, dy = py - c1.y, dz = pz - c1.z;
            float s2 = fmaf(dx, dx, fmaf(dy, dy, dz * dz));
            float cc = __fsqrt_rn(s2);
            float e  = exp2f(K0_CONST * fabsf(cc - m1));
            s1 = (cc < m1) ? fmaf(s1, e, 1.0f) : (s1 + e);
            m1 = fminf(m1, cc);
        }
    }
    if (j < count) {
        float4 c0 = __ldg(&cand[j]);
        float dx = px - c0.x, dy = py - c0.y, dz = pz - c0.z;
        float s2 = fmaf(dx, dx, fmaf(dy, dy, dz * dz));
        float cc = __fsqrt_rn(s2);
        float e  = exp2f(K0_CONST * fabsf(cc - m0));
        s0 = (cc < m0) ? fmaf(s0, e, 1.0f) : (s0 + e);
        m0 = fminf(m0, cc);
    }

    // Merge the two accumulators
    {
        float mn = fminf(m0, m1);
        s0 = s0 * exp2f(K0_CONST * (m0 - mn))
           + s1 * exp2f(K0_CONST * (m1 - mn));
        m0 = mn;
    }

    // Warp-level (m, s) combine
    #pragma unroll
    for (int off = 16; off > 0; off >>= 1) {
        float mo = __shfl_xor_sync(0xffffffffu, m0, off);
        float so = __shfl_xor_sync(0xffffffffu, s0, off);
        float mn = fminf(m0, mo);
        s0 = s0 * exp2f(K0_CONST * (m0 - mn))
           + so * exp2f(K0_CONST * (mo - mn));
        m0 = mn;
    }
    if (lane == 0) { sh_m[warp] = m0; sh_s[warp] = s0; }
    __syncthreads();

    if (tid == 0) {
        float M0 = sh_m[0], S0 = sh_s[0];
        #pragma unroll
        for (int w = 1; w < NWARPS; ++w) {
            float mo = sh_m[w], so = sh_s[w];
            float mn = fminf(M0, mo);
            S0 = S0 * exp2f(K0_CONST * (M0 - mn))
               + so * exp2f(K0_CONST * (mo - mn));
            M0 = mn;
        }
        float soft = 0.0f;
        if (count > 0) {
            float d_min = (2.0f * EARTH_R) * asinf(fminf(0.5f * M0, 1.0f));
            soft = d_min - 0.25f * logf(S0);
        }
        g_sv[b] = make_float2(soft, (count > 0) ? 1.0f : 0.0f);
    }
}

// ---------------------------------------------------------------------------
// Kernel 3: deterministic single-block reduction (separate launch = full
// visibility; fixed summation order). Reads g_sv as float4 (2 rows/load).
// ---------------------------------------------------------------------------
__global__ __launch_bounds__(1024)
void softbin_reduce_kernel(float* __restrict__ out) {
    __shared__ float rs[1024];
    __shared__ float rv[1024];
    const int tid = threadIdx.x;
    const float4* __restrict__ sv4 = (const float4*)g_sv;  // 16B-aligned global
    float ss = 0.0f, vv = 0.0f;
    #pragma unroll
    for (int i = tid; i < B_ROWS / 2; i += 1024) {
        float4 v = __ldg(&sv4[i]);      // (soft0, valid0, soft1, valid1)
        ss += v.x + v.z;
        vv += v.y + v.w;
    }
    rs[tid] = ss;
    rv[tid] = vv;
    __syncthreads();
    #pragma unroll
    for (int off = 512; off > 0; off >>= 1) {
        if (tid < off) {
            rs[tid] += rs[tid + off];
            rv[tid] += rv[tid + off];
        }
        __syncthreads();
    }
    if (tid == 0) out[0] = rs[0] / fmaxf(rv[0], 1.0f);
}

extern "C" void kernel_launch(void* const* d_in, const int* in_sizes, int n_in,
                              void* d_out, int out_size) {
    // Identify inputs by element count (all four are distinct).
    const float*     preds      = 0;   // 16384
    const float2*    bin_coords = 0;   // 1024000
    const long long* x_vals     = 0;   // 24576
    const long long* bin_counts = 0;   // 125
    for (int i = 0; i < n_in; ++i) {
        switch (in_sizes[i]) {
            case 16384:   preds      = (const float*)d_in[i];     break;
            case 1024000: bin_coords = (const float2*)d_in[i];    break;
            case 24576:   x_vals     = (const long long*)d_in[i]; break;
            case 125:     bin_counts = (const long long*)d_in[i]; break;
        }
    }
    float* out = (float*)d_out;

    prep_kernel<<<(NTOT + B_ROWS + 255) / 256, 256>>>(bin_coords, preds, x_vals, bin_counts);
    softbin_main_kernel<<<B_ROWS, NTHREADS>>>();
    softbin_reduce_kernel<<<1, 1024>>>(out);
}